// round 7
// baseline (speedup 1.0000x reference)
#include <cuda_runtime.h>
#include <cstdint>

#define PB 4
#define PN 16384
#define PS 2048
#define PC 64
#define PK 33
#define PNS 32
#define JTOT (PS * PK)        // 67584
#define OUTC (6 + PC)         // 70
#define GR 10
#define NC (GR * GR * GR)     // 1000
#define BPB 32                // hist/scatter blocks per batch
#define NBLK (PB * BPB)       // 128
#define PTS_PER_BLK (PN / BPB)  // 512
#define CAP 256
#define TJ 128

__device__ int    g_idx[PB * PS * PK];
__device__ float4 g_featT4[(size_t)PB * PN * PC / 4];
__device__ int    g_cellStart[PB * (NC + 1)];
__device__ int    g_hist[NBLK * NC];
__device__ int    g_blockBase[NBLK * NC];
__device__ float4 g_pts[PB * PN];   // grid-reordered {x,y,z,bitcast(idx)}

__device__ __forceinline__ int cell_of(float x, float y, float z) {
    int ix = min((int)(x * 10.0f), GR - 1);
    int iy = min((int)(y * 10.0f), GR - 1);
    int iz = min((int)(z * 10.0f), GR - 1);
    return (iz * GR + iy) * GR + ix;
}

// ---------------------------------------------------------------------------
// Grid build: per-block histograms (atomic-free across blocks)
// ---------------------------------------------------------------------------
__global__ void __launch_bounds__(256) hist_cells(const float* __restrict__ xyz) {
    __shared__ int sh[NC];
    int blk = blockIdx.x;               // 0..127
    int b   = blk / BPB;
    int t   = threadIdx.x;
    for (int i = t; i < NC; i += 256) sh[i] = 0;
    __syncthreads();
    const float* xb = xyz + ((size_t)b * PN + (blk % BPB) * PTS_PER_BLK) * 3;
#pragma unroll
    for (int k = 0; k < PTS_PER_BLK / 256; k++) {
        const float* p = xb + 3 * (t + k * 256);
        atomicAdd(&sh[cell_of(p[0], p[1], p[2])], 1);
    }
    __syncthreads();
    for (int i = t; i < NC; i += 256) g_hist[blk * NC + i] = sh[i];
}

// Per-batch scan -> cellStart + per-block scatter bases (two-pass, no reg array)
__global__ void __launch_bounds__(1024) scan_cells() {
    __shared__ int s[1024];
    int b = blockIdx.x;
    int t = threadIdx.x;
    int tot = 0;
    if (t < NC) {
        for (int i = 0; i < BPB; i++) tot += g_hist[(b * BPB + i) * NC + t];
    }
    s[t] = tot;
    __syncthreads();
#pragma unroll
    for (int off = 1; off < 1024; off <<= 1) {
        int v = (t >= off) ? s[t - off] : 0;
        __syncthreads();
        if (t >= off) s[t] += v;
        __syncthreads();
    }
    if (t < NC) {
        int excl = s[t] - tot;
        g_cellStart[b * (NC + 1) + t] = excl;
        if (t == NC - 1) g_cellStart[b * (NC + 1) + NC] = s[t];
        int rb = excl;
        for (int i = 0; i < BPB; i++) {               // hist rows L2-hot
            g_blockBase[(b * BPB + i) * NC + t] = rb;
            rb += g_hist[(b * BPB + i) * NC + t];
        }
    }
}

// Scatter using smem cursors seeded from per-block bases
__global__ void __launch_bounds__(256) scatter_pts(const float* __restrict__ xyz) {
    __shared__ int scur[NC];
    int blk = blockIdx.x;
    int b   = blk / BPB;
    int t   = threadIdx.x;
    for (int i = t; i < NC; i += 256) scur[i] = g_blockBase[blk * NC + i];
    __syncthreads();
    int nbase = (blk % BPB) * PTS_PER_BLK;
    const float* xb = xyz + ((size_t)b * PN + nbase) * 3;
    float4* pb = g_pts + (size_t)b * PN;
#pragma unroll
    for (int k = 0; k < PTS_PER_BLK / 256; k++) {
        int n = t + k * 256;
        const float* p = xb + 3 * n;
        float x = p[0], y = p[1], z = p[2];
        int pos = atomicAdd(&scur[cell_of(x, y, z)], 1);
        pb[pos] = make_float4(x, y, z, __int_as_float(nbase + n));
    }
}

// ---------------------------------------------------------------------------
// Ball query (one batch per launch) — one warp per query; rank-select 32
// smallest hit indices. Order-independent of scatter order.
// ---------------------------------------------------------------------------
__global__ void __launch_bounds__(256) ball_query_grid(const float* __restrict__ new_xyz,
                                                       const int*   __restrict__ fps,
                                                       int b) {
    __shared__ int buf[8][264];
    int wi   = threadIdx.x >> 5;
    int lane = threadIdx.x & 31;
    int s    = blockIdx.x * 8 + wi;     // 0..2047

    const float* q = new_xyz + ((size_t)b * PS + s) * 3;
    float qx = q[0], qy = q[1], qz = q[2];
    int* out = g_idx + ((size_t)b * PS + s) * PK;
    if (lane == 0) out[0] = fps[b * PS + s];

    int cx = min((int)(qx * 10.0f), GR - 1);
    int cy = min((int)(qy * 10.0f), GR - 1);
    int cz = min((int)(qz * 10.0f), GR - 1);

    const float4* pts = g_pts + (size_t)b * PN;
    const int*    cst = g_cellStart + (size_t)b * (NC + 1);
    int* wbuf = buf[wi];

    const float R2 = 0.01f;   // (float)(0.1*0.1 in f64) == 0.01f
    const unsigned FULL = 0xffffffffu;
    int cnt = 0;

    int z0 = max(cz - 1, 0), z1 = min(cz + 1, GR - 1);
    int y0 = max(cy - 1, 0), y1 = min(cy + 1, GR - 1);
    int x0 = max(cx - 1, 0), x1 = min(cx + 1, GR - 1);

    for (int zz = z0; zz <= z1; zz++) {
        for (int yy = y0; yy <= y1; yy++) {
            int cbase = (zz * GR + yy) * GR;
            int beg = cst[cbase + x0];
            int end = cst[cbase + x1 + 1];
            for (; beg < end; beg += 32) {
                int i = beg + lane;
                bool hit = false;
                int pid = 0;
                if (i < end) {
                    float4 v = pts[i];
                    float dx = __fsub_rn(qx, v.x);
                    float dy = __fsub_rn(qy, v.y);
                    float dz = __fsub_rn(qz, v.z);
                    float d2 = __fadd_rn(__fadd_rn(__fmul_rn(dx, dx), __fmul_rn(dy, dy)),
                                         __fmul_rn(dz, dz));
                    hit = d2 < R2;
                    pid = __float_as_int(v.w);
                }
                unsigned m = __ballot_sync(FULL, hit);
                if (hit) {
                    int pos = cnt + __popc(m & ((1u << lane) - 1u));
                    if (pos < CAP) wbuf[pos] = pid;
                }
                cnt += __popc(m);
            }
        }
    }

    int M  = min(cnt, CAP);
    int Mp = (M + 3) & ~3;
    if (lane < Mp - M) wbuf[M + lane] = 0x7fffffff;
    __syncwarp();

    int minhit = 0x7fffffff;
    const int4* b4 = (const int4*)wbuf;
    for (int i = lane; i < M; i += 32) {
        int h = wbuf[i];
        minhit = min(minhit, h);
        int rank = 0;
        int nq = Mp >> 2;
        for (int j = 0; j < nq; j++) {
            int4 w = b4[j];
            rank += (w.x < h) + (w.y < h) + (w.z < h) + (w.w < h);
        }
        if (rank < PNS) out[1 + rank] = h;
    }
#pragma unroll
    for (int off = 16; off; off >>= 1)
        minhit = min(minhit, __shfl_xor_sync(FULL, minhit, off));
    int fill = (cnt == 0) ? 0 : minhit;
    int c = min(cnt, PNS);
    if (lane >= c) out[1 + lane] = fill;
}

// ---------------------------------------------------------------------------
// Transpose features (B, C, N) -> (B, N, C). 64x64 tiles, float4 both ways.
// ---------------------------------------------------------------------------
__global__ void __launch_bounds__(256) transpose_feat(const float* __restrict__ f) {
    __shared__ float tile[64][65];
    int b  = blockIdx.y;
    int n0 = blockIdx.x * 64;
    const float* fb = f + (size_t)b * PC * PN;
    float4*     ftb = g_featT4 + (size_t)b * PN * (PC / 4);
    int t  = threadIdx.x;
    int qd = t & 15;
    int r0 = t >> 4;
#pragma unroll
    for (int k = 0; k < 4; k++) {
        int c = r0 + k * 16;
        float4 v = *(const float4*)(fb + (size_t)c * PN + n0 + qd * 4);
        tile[c][qd * 4 + 0] = v.x;
        tile[c][qd * 4 + 1] = v.y;
        tile[c][qd * 4 + 2] = v.z;
        tile[c][qd * 4 + 3] = v.w;
    }
    __syncthreads();
#pragma unroll
    for (int k = 0; k < 4; k++) {
        int n = r0 + k * 16;
        float4 v;
        v.x = tile[qd * 4 + 0][n];
        v.y = tile[qd * 4 + 1][n];
        v.z = tile[qd * 4 + 2][n];
        v.w = tile[qd * 4 + 3][n];
        ftb[(size_t)(n0 + n) * (PC / 4) + qd] = v;
    }
}

// ---------------------------------------------------------------------------
// Gather + write (one batch per launch): 128 j per block, 528 blocks.
// ---------------------------------------------------------------------------
__global__ void __launch_bounds__(256) gather_write(const float* __restrict__ xyz,
                                                    const float* __restrict__ new_xyz,
                                                    float* __restrict__ out, int b) {
    __shared__ float tile[TJ][PC + 1];
    __shared__ int   sn[TJ];
    __shared__ float sxyz[TJ][3];
    __shared__ float sctr[TJ][3];

    int j0  = blockIdx.x * TJ;
    int tid = threadIdx.x;

    if (tid < TJ) {
        int j = j0 + tid;
        int n = g_idx[(size_t)b * JTOT + j];
        sn[tid] = n;
        int s = j / PK;
        const float* p = xyz     + ((size_t)b * PN + n) * 3;
        const float* q = new_xyz + ((size_t)b * PS + s) * 3;
        float x = p[0], y = p[1], z = p[2];
        sxyz[tid][0] = x;         sxyz[tid][1] = y;         sxyz[tid][2] = z;
        sctr[tid][0] = x - q[0];  sctr[tid][1] = y - q[1];  sctr[tid][2] = z - q[2];
    }
    __syncthreads();

    const float4* ftb = g_featT4 + (size_t)b * PN * (PC / 4);
#pragma unroll
    for (int it = 0; it < 8; it++) {
        int lin = tid + it * 256;
        int jj  = lin >> 4;
        int qd  = lin & 15;
        float4 v = ftb[(size_t)sn[jj] * (PC / 4) + qd];
        tile[jj][qd * 4 + 0] = v.x;
        tile[jj][qd * 4 + 1] = v.y;
        tile[jj][qd * 4 + 2] = v.z;
        tile[jj][qd * 4 + 3] = v.w;
    }
    __syncthreads();

    float* ob = out + (size_t)b * OUTC * JTOT + j0;
#pragma unroll
    for (int it = 0; it < 3; it++) {
        int idx  = it * 256 + tid;
        int c    = idx >> 7;
        int jpos = idx & (TJ - 1);
        float v = (c < 3) ? sxyz[jpos][c] : sctr[jpos][c - 3];
        ob[(size_t)c * JTOT + jpos] = v;
    }
#pragma unroll
    for (int it = 0; it < 32; it++) {
        int idx  = it * 256 + tid;
        int c    = idx >> 7;
        int jpos = idx & (TJ - 1);
        ob[(size_t)(6 + c) * JTOT + jpos] = tile[jpos][c];
    }
}

// ---------------------------------------------------------------------------
extern "C" void kernel_launch(void* const* d_in, const int* in_sizes, int n_in,
                              void* d_out, int out_size) {
    const float* xyz      = (const float*)d_in[0];
    const float* new_xyz  = (const float*)d_in[1];
    const float* features = (const float*)d_in[2];
    const int*   fps_idx  = (const int*)  d_in[3];
    float* out = (float*)d_out;

    static cudaStream_t sT = nullptr, sG = nullptr;
    static cudaEvent_t evFork = nullptr, evT = nullptr, evG = nullptr;
    static cudaEvent_t evB[PB] = {nullptr, nullptr, nullptr, nullptr};
    if (!sT) {
        cudaStreamCreateWithFlags(&sT, cudaStreamNonBlocking);
        cudaStreamCreateWithFlags(&sG, cudaStreamNonBlocking);
        cudaEventCreateWithFlags(&evFork, cudaEventDisableTiming);
        cudaEventCreateWithFlags(&evT, cudaEventDisableTiming);
        cudaEventCreateWithFlags(&evG, cudaEventDisableTiming);
        for (int b = 0; b < PB; b++)
            cudaEventCreateWithFlags(&evB[b], cudaEventDisableTiming);
    }

    // Fork transpose: concurrent with grid build + ball queries
    cudaEventRecord(evFork, 0);
    cudaStreamWaitEvent(sT, evFork, 0);
    {
        dim3 grid(PN / 64, PB);
        transpose_feat<<<grid, 256, 0, sT>>>(features);
    }
    cudaEventRecord(evT, sT);

    // Grid build (atomic-free across blocks)
    hist_cells<<<NBLK, 256>>>(xyz);
    scan_cells<<<PB, 1024>>>();
    scatter_pts<<<NBLK, 256>>>(xyz);

    // Batch-pipelined ball query (stream 0) -> gather (stream sG)
    cudaStreamWaitEvent(sG, evT, 0);   // gathers need featT
    for (int b = 0; b < PB; b++) {
        ball_query_grid<<<PS / 8, 256>>>(new_xyz, fps_idx, b);
        cudaEventRecord(evB[b], 0);
        cudaStreamWaitEvent(sG, evB[b], 0);
        gather_write<<<JTOT / TJ, 256, 0, sG>>>(xyz, new_xyz, out, b);
    }

    // Join gather stream back into the default stream
    cudaEventRecord(evG, sG);
    cudaStreamWaitEvent(0, evG, 0);
}

// round 8
// speedup vs baseline: 1.3130x; 1.3130x over previous
#include <cuda_runtime.h>
#include <cstdint>

#define PB 4
#define PN 16384
#define PS 2048
#define PC 64
#define PK 33
#define PNS 32
#define JTOT (PS * PK)        // 67584
#define OUTC (6 + PC)         // 70
#define GR 10
#define NC (GR * GR * GR)     // 1000
#define BPB 32                // hist/scatter blocks per batch
#define NBLK (PB * BPB)       // 128
#define PTS_PER_BLK (PN / BPB)  // 512
#define CAP 256
#define TJ 128

__device__ int    g_idx[PB * PS * PK];
__device__ float4 g_featT4[(size_t)PB * PN * PC / 4];
__device__ int    g_cellStart[PB * (NC + 1)];
__device__ int    g_hist[NBLK * NC];
__device__ int    g_blockBase[NBLK * NC];
__device__ float4 g_pts[PB * PN];   // grid-reordered {x,y,z,bitcast(idx)}

__device__ __forceinline__ int cell_of(float x, float y, float z) {
    int ix = min((int)(x * 10.0f), GR - 1);
    int iy = min((int)(y * 10.0f), GR - 1);
    int iz = min((int)(z * 10.0f), GR - 1);
    return (iz * GR + iy) * GR + ix;
}

// ---------------------------------------------------------------------------
// Grid build: per-block histograms (atomic-free across blocks)
// ---------------------------------------------------------------------------
__global__ void __launch_bounds__(256) hist_cells(const float* __restrict__ xyz) {
    __shared__ int sh[NC];
    int blk = blockIdx.x;
    int b   = blk / BPB;
    int t   = threadIdx.x;
    for (int i = t; i < NC; i += 256) sh[i] = 0;
    __syncthreads();
    const float* xb = xyz + ((size_t)b * PN + (blk % BPB) * PTS_PER_BLK) * 3;
#pragma unroll
    for (int k = 0; k < PTS_PER_BLK / 256; k++) {
        const float* p = xb + 3 * (t + k * 256);
        atomicAdd(&sh[cell_of(p[0], p[1], p[2])], 1);
    }
    __syncthreads();
    for (int i = t; i < NC; i += 256) g_hist[blk * NC + i] = sh[i];
}

// Per-batch scan -> cellStart + per-block scatter bases
__global__ void __launch_bounds__(1024) scan_cells() {
    __shared__ int s[1024];
    int b = blockIdx.x;
    int t = threadIdx.x;
    int tot = 0;
    if (t < NC) {
        for (int i = 0; i < BPB; i++) tot += g_hist[(b * BPB + i) * NC + t];
    }
    s[t] = tot;
    __syncthreads();
#pragma unroll
    for (int off = 1; off < 1024; off <<= 1) {
        int v = (t >= off) ? s[t - off] : 0;
        __syncthreads();
        if (t >= off) s[t] += v;
        __syncthreads();
    }
    if (t < NC) {
        int excl = s[t] - tot;
        g_cellStart[b * (NC + 1) + t] = excl;
        if (t == NC - 1) g_cellStart[b * (NC + 1) + NC] = s[t];
        int rb = excl;
        for (int i = 0; i < BPB; i++) {
            g_blockBase[(b * BPB + i) * NC + t] = rb;
            rb += g_hist[(b * BPB + i) * NC + t];
        }
    }
}

// Scatter using smem cursors seeded from per-block bases
__global__ void __launch_bounds__(256) scatter_pts(const float* __restrict__ xyz) {
    __shared__ int scur[NC];
    int blk = blockIdx.x;
    int b   = blk / BPB;
    int t   = threadIdx.x;
    for (int i = t; i < NC; i += 256) scur[i] = g_blockBase[blk * NC + i];
    __syncthreads();
    int nbase = (blk % BPB) * PTS_PER_BLK;
    const float* xb = xyz + ((size_t)b * PN + nbase) * 3;
    float4* pb = g_pts + (size_t)b * PN;
#pragma unroll
    for (int k = 0; k < PTS_PER_BLK / 256; k++) {
        int n = t + k * 256;
        const float* p = xb + 3 * n;
        float x = p[0], y = p[1], z = p[2];
        int pos = atomicAdd(&scur[cell_of(x, y, z)], 1);
        pb[pos] = make_float4(x, y, z, __int_as_float(nbase + n));
    }
}

// ---------------------------------------------------------------------------
// Ball query — one warp per query; DENSE candidate packing over the up-to-9
// contiguous cell-row segments (hit order irrelevant: rank-select follows).
// ---------------------------------------------------------------------------
__global__ void __launch_bounds__(256) ball_query_grid(const float* __restrict__ new_xyz,
                                                       const int*   __restrict__ fps) {
    __shared__ int buf[8][264];
    __shared__ int scum[8][10];   // cum[k] = end of segment k in virtual idx space
    __shared__ int sadj[8][10];   // adj[k] = segBeg - cumStart (i = adj + idx)
    int wi   = threadIdx.x >> 5;
    int lane = threadIdx.x & 31;
    int gw   = blockIdx.x * 8 + wi;
    int b = gw >> 11;
    int s = gw & (PS - 1);

    const float* q = new_xyz + ((size_t)b * PS + s) * 3;
    float qx = q[0], qy = q[1], qz = q[2];
    int* out = g_idx + ((size_t)b * PS + s) * PK;
    if (lane == 0) out[0] = fps[b * PS + s];

    int cx = min((int)(qx * 10.0f), GR - 1);
    int cy = min((int)(qy * 10.0f), GR - 1);
    int cz = min((int)(qz * 10.0f), GR - 1);

    const float4* pts = g_pts + (size_t)b * PN;
    const int*    cst = g_cellStart + (size_t)b * (NC + 1);
    int* wbuf = buf[wi];
    int* cum  = scum[wi];
    int* adj  = sadj[wi];

    int z0 = max(cz - 1, 0), z1 = min(cz + 1, GR - 1);
    int y0 = max(cy - 1, 0), y1 = min(cy + 1, GR - 1);
    int x0 = max(cx - 1, 0), x1 = min(cx + 1, GR - 1);

    // Build flattened segment table (warp-uniform; lane 0 stores)
    int nseg = 0, T = 0;
    for (int zz = z0; zz <= z1; zz++) {
        for (int yy = y0; yy <= y1; yy++) {
            int cbase = (zz * GR + yy) * GR;
            int beg = cst[cbase + x0];
            int end = cst[cbase + x1 + 1];
            int len = end - beg;
            if (len > 0) {
                if (lane == 0) { adj[nseg] = beg - T; cum[nseg] = T + len; }
                nseg++;
                T += len;
            }
        }
    }
    __syncwarp();

    const float R2 = 0.01f;   // (float)(0.1*0.1 in f64) == 0.01f
    const unsigned FULL = 0xffffffffu;
    int cnt = 0;
    int seg = 0;              // per-lane monotone segment pointer

    for (int base = 0; base < T; base += 32) {
        int idx = base + lane;
        bool hit = false;
        int pid = 0;
        if (idx < T) {
            while (idx >= cum[seg]) seg++;
            float4 v = pts[adj[seg] + idx];
            float dx = __fsub_rn(qx, v.x);
            float dy = __fsub_rn(qy, v.y);
            float dz = __fsub_rn(qz, v.z);
            float d2 = __fadd_rn(__fadd_rn(__fmul_rn(dx, dx), __fmul_rn(dy, dy)),
                                 __fmul_rn(dz, dz));
            hit = d2 < R2;
            pid = __float_as_int(v.w);
        }
        unsigned m = __ballot_sync(FULL, hit);
        if (hit) {
            int pos = cnt + __popc(m & ((1u << lane) - 1u));
            if (pos < CAP) wbuf[pos] = pid;
        }
        cnt += __popc(m);
    }

    int M  = min(cnt, CAP);
    int Mp = (M + 3) & ~3;
    if (lane < Mp - M) wbuf[M + lane] = 0x7fffffff;
    __syncwarp();

    int minhit = 0x7fffffff;
    const int4* b4 = (const int4*)wbuf;
    for (int i = lane; i < M; i += 32) {
        int h = wbuf[i];
        minhit = min(minhit, h);
        int rank = 0;
        int nq = Mp >> 2;
        for (int j = 0; j < nq; j++) {
            int4 w = b4[j];
            rank += (w.x < h) + (w.y < h) + (w.z < h) + (w.w < h);
        }
        if (rank < PNS) out[1 + rank] = h;
    }
#pragma unroll
    for (int off = 16; off; off >>= 1)
        minhit = min(minhit, __shfl_xor_sync(FULL, minhit, off));
    int fill = (cnt == 0) ? 0 : minhit;
    int c = min(cnt, PNS);
    if (lane >= c) out[1 + lane] = fill;
}

// ---------------------------------------------------------------------------
// Transpose features (B, C, N) -> (B, N, C). 64x64 tiles, float4 both ways.
// ---------------------------------------------------------------------------
__global__ void __launch_bounds__(256) transpose_feat(const float* __restrict__ f) {
    __shared__ float tile[64][65];
    int b  = blockIdx.y;
    int n0 = blockIdx.x * 64;
    const float* fb = f + (size_t)b * PC * PN;
    float4*     ftb = g_featT4 + (size_t)b * PN * (PC / 4);
    int t  = threadIdx.x;
    int qd = t & 15;
    int r0 = t >> 4;
#pragma unroll
    for (int k = 0; k < 4; k++) {
        int c = r0 + k * 16;
        float4 v = *(const float4*)(fb + (size_t)c * PN + n0 + qd * 4);
        tile[c][qd * 4 + 0] = v.x;
        tile[c][qd * 4 + 1] = v.y;
        tile[c][qd * 4 + 2] = v.z;
        tile[c][qd * 4 + 3] = v.w;
    }
    __syncthreads();
#pragma unroll
    for (int k = 0; k < 4; k++) {
        int n = r0 + k * 16;
        float4 v;
        v.x = tile[qd * 4 + 0][n];
        v.y = tile[qd * 4 + 1][n];
        v.z = tile[qd * 4 + 2][n];
        v.w = tile[qd * 4 + 3][n];
        ftb[(size_t)(n0 + n) * (PC / 4) + qd] = v;
    }
}

// ---------------------------------------------------------------------------
// Gather + write: 128 j per block, 2112 blocks. Streaming (__stcs) output.
// ---------------------------------------------------------------------------
__global__ void __launch_bounds__(256) gather_write(const float* __restrict__ xyz,
                                                    const float* __restrict__ new_xyz,
                                                    float* __restrict__ out) {
    __shared__ float tile[TJ][PC + 1];
    __shared__ int   sn[TJ];
    __shared__ float sxyz[TJ][3];
    __shared__ float sq[TJ][3];

    int bj  = blockIdx.x;
    int b   = bj / (JTOT / TJ);
    int j0  = (bj - b * (JTOT / TJ)) * TJ;
    int tid = threadIdx.x;

    // Phase 1: all 256 threads busy — low half: idx+point xyz; high half: query xyz
    if (tid < TJ) {
        int j = j0 + tid;
        int n = g_idx[(size_t)b * JTOT + j];
        sn[tid] = n;
        const float* p = xyz + ((size_t)b * PN + n) * 3;
        sxyz[tid][0] = p[0];  sxyz[tid][1] = p[1];  sxyz[tid][2] = p[2];
    } else {
        int jt = tid - TJ;
        int s  = (j0 + jt) / PK;
        const float* qp = new_xyz + ((size_t)b * PS + s) * 3;
        sq[jt][0] = qp[0];  sq[jt][1] = qp[1];  sq[jt][2] = qp[2];
    }
    __syncthreads();

    const float4* ftb = g_featT4 + (size_t)b * PN * (PC / 4);
#pragma unroll
    for (int it = 0; it < 8; it++) {
        int lin = tid + it * 256;
        int jj  = lin >> 4;
        int qd  = lin & 15;
        float4 v = ftb[(size_t)sn[jj] * (PC / 4) + qd];
        tile[jj][qd * 4 + 0] = v.x;
        tile[jj][qd * 4 + 1] = v.y;
        tile[jj][qd * 4 + 2] = v.z;
        tile[jj][qd * 4 + 3] = v.w;
    }
    __syncthreads();

    float* ob = out + (size_t)b * OUTC * JTOT + j0;

    // xyz channels 0..5 (raw then centered); streaming stores
#pragma unroll
    for (int it = 0; it < 3; it++) {
        int idx  = it * 256 + tid;
        int c    = idx >> 7;
        int jpos = idx & (TJ - 1);
        float v = (c < 3) ? sxyz[jpos][c] : (sxyz[jpos][c - 3] - sq[jpos][c - 3]);
        __stcs(&ob[(size_t)c * JTOT + jpos], v);
    }
    // feature channels; conflict-free LDS, streaming stores
#pragma unroll
    for (int it = 0; it < 32; it++) {
        int idx  = it * 256 + tid;
        int c    = idx >> 7;
        int jpos = idx & (TJ - 1);
        __stcs(&ob[(size_t)(6 + c) * JTOT + jpos], tile[jpos][c]);
    }
}

// ---------------------------------------------------------------------------
extern "C" void kernel_launch(void* const* d_in, const int* in_sizes, int n_in,
                              void* d_out, int out_size) {
    const float* xyz      = (const float*)d_in[0];
    const float* new_xyz  = (const float*)d_in[1];
    const float* features = (const float*)d_in[2];
    const int*   fps_idx  = (const int*)  d_in[3];
    float* out = (float*)d_out;

    static cudaStream_t sT = nullptr;
    static cudaEvent_t evFork = nullptr, evT = nullptr;
    if (!sT) {
        cudaStreamCreateWithFlags(&sT, cudaStreamNonBlocking);
        cudaEventCreateWithFlags(&evFork, cudaEventDisableTiming);
        cudaEventCreateWithFlags(&evT, cudaEventDisableTiming);
    }

    // Fork: transpose concurrent with grid build + ball query
    cudaEventRecord(evFork, 0);
    cudaStreamWaitEvent(sT, evFork, 0);
    {
        dim3 grid(PN / 64, PB);
        transpose_feat<<<grid, 256, 0, sT>>>(features);
    }
    cudaEventRecord(evT, sT);

    // Grid build
    hist_cells<<<NBLK, 256>>>(xyz);
    scan_cells<<<PB, 1024>>>();
    scatter_pts<<<NBLK, 256>>>(xyz);

    // Ball query (all batches, 1024 blocks)
    ball_query_grid<<<PB * PS / 8, 256>>>(new_xyz, fps_idx);

    // Join, then gather + write (all batches, 2112 blocks)
    cudaStreamWaitEvent(0, evT, 0);
    gather_write<<<PB * (JTOT / TJ), 256>>>(xyz, new_xyz, out);
}